// round 3
// baseline (speedup 1.0000x reference)
#include <cuda_runtime.h>
#include <cstdint>

#define BATCH  4
#define N_PTS  16384
#define N_SAMP 1024
#define K_NEI  32
#define C_FEAT 128
#define CL     8               // cluster size (CTAs per batch)
#define TPB    1024
#define PPT    2               // N_PTS / (CL*TPB)

// scratch: neighbor indices (device global -> no allocation)
__device__ int g_nidx[BATCH * N_SAMP * K_NEI];

// ---------------- threefry2x32 (JAX-compatible, both output words) ----------------
__device__ __forceinline__ uint32_t rotl32(uint32_t x, int r) {
    return (x << r) | (x >> (32 - r));
}

__device__ __forceinline__ void threefry2x32(uint32_t k0, uint32_t k1,
                                             uint32_t x0, uint32_t x1,
                                             uint32_t& o0, uint32_t& o1) {
    uint32_t ks2 = k0 ^ k1 ^ 0x1BD11BDAu;
    x0 += k0; x1 += k1;
#define TF_RND(r) { x0 += x1; x1 = rotl32(x1, (r)); x1 ^= x0; }
    TF_RND(13) TF_RND(15) TF_RND(26) TF_RND(6)   x0 += k1;  x1 += ks2 + 1u;
    TF_RND(17) TF_RND(29) TF_RND(16) TF_RND(24)  x0 += ks2; x1 += k0 + 2u;
    TF_RND(13) TF_RND(15) TF_RND(26) TF_RND(6)   x0 += k0;  x1 += k1 + 3u;
    TF_RND(17) TF_RND(29) TF_RND(16) TF_RND(24)  x0 += k1;  x1 += ks2 + 4u;
    TF_RND(13) TF_RND(15) TF_RND(26) TF_RND(6)   x0 += ks2; x1 += k0 + 5u;
#undef TF_RND
    o0 = x0; o1 = x1;
}

// start index for batch b, replicating JAX with threefry_partitionable=True
// (default since JAX 0.4.36):
//   k1,k2 = split(key(42))          [foldlike: k2 = tf2x32((0,42),(0,1)) pair]
//   lower_bits = random_bits(k2,32,(4,)) [partitionable: bits_b = o0^o1 of
//                                         tf2x32(k2,(0,b))]
//   start = lower_bits % 16384      [span = power of two -> multiplier = 0]
__device__ __forceinline__ int jax_start_idx(int b) {
    uint32_t k2a, k2b;
    threefry2x32(0u, 42u, 0u, 1u, k2a, k2b);
    uint32_t o0, o1;
    threefry2x32(k2a, k2b, 0u, (uint32_t)b, o0, o1);
    return (int)((o0 ^ o1) & (uint32_t)(N_PTS - 1));
}

// ---------------- cluster DSMEM helpers ----------------
__device__ __forceinline__ void st_peer_f32(uint32_t laddr, uint32_t peer, float v) {
    uint32_t r;
    asm volatile("mapa.shared::cluster.u32 %0, %1, %2;" : "=r"(r) : "r"(laddr), "r"(peer));
    asm volatile("st.shared::cluster.f32 [%0], %1;" :: "r"(r), "f"(v) : "memory");
}
__device__ __forceinline__ void st_peer_s32(uint32_t laddr, uint32_t peer, int v) {
    uint32_t r;
    asm volatile("mapa.shared::cluster.u32 %0, %1, %2;" : "=r"(r) : "r"(laddr), "r"(peer));
    asm volatile("st.shared::cluster.s32 [%0], %1;" :: "r"(r), "r"(v) : "memory");
}

// ---------------- FPS: one 8-CTA cluster per batch ----------------
__global__ void __cluster_dims__(CL, 1, 1) fps_kernel(const float* __restrict__ xyz,
                                                      float* __restrict__ out_xyz) {
    const int b = blockIdx.x / CL;
    uint32_t rank;
    asm("mov.u32 %0, %%cluster_ctarank;" : "=r"(rank));
    const float* __restrict__ X = xyz + (size_t)b * N_PTS * 3;
    const int t = threadIdx.x;
    const int base = (int)rank * (TPB * PPT);
    const int w = t >> 5, lane = t & 31;

    // register-resident points + running min distance
    float px[PPT], py[PPT], pz[PPT], md[PPT];
#pragma unroll
    for (int j = 0; j < PPT; j++) {
        int i = base + j * TPB + t;
        px[j] = X[3 * i + 0];
        py[j] = X[3 * i + 1];
        pz[j] = X[3 * i + 2];
        md[j] = __int_as_float(0x7f800000);  // +inf
    }

    __shared__ float s_wv[32], s_wx[32], s_wy[32], s_wz[32];
    __shared__ int   s_wi[32];
    // cross-CTA candidate slots, double-buffered by step parity
    __shared__ float c_v[2][CL], c_x[2][CL], c_y[2][CL], c_z[2][CL];
    __shared__ int   c_i[2][CL];

    int cur = jax_start_idx(b);
    float qx = X[3 * cur + 0], qy = X[3 * cur + 1], qz = X[3 * cur + 2];

    for (int s = 0; s < N_SAMP; s++) {
        if (rank == 0 && t == 0) {
            float* o = out_xyz + ((size_t)b * N_SAMP + s) * 3;
            o[0] = qx; o[1] = qy; o[2] = qz;
        }
        if (s == N_SAMP - 1) break;

        // update min-dist and track local argmax (carry coords).
        // EXACT arithmetic: no FMA contraction, left-assoc sum (matches XLA).
        float bv = -1.0f, bx = 0.f, by = 0.f, bz = 0.f;
        int bi = 0;
#pragma unroll
        for (int j = 0; j < PPT; j++) {
            float dx = __fsub_rn(px[j], qx);
            float dy = __fsub_rn(py[j], qy);
            float dz = __fsub_rn(pz[j], qz);
            float d2 = __fadd_rn(__fadd_rn(__fmul_rn(dx, dx), __fmul_rn(dy, dy)),
                                 __fmul_rn(dz, dz));
            float m = fminf(md[j], d2);
            md[j] = m;
            if (m > bv) {  // strict > keeps smallest index within thread
                bv = m; bi = base + j * TPB + t;
                bx = px[j]; by = py[j]; bz = pz[j];
            }
        }
        // warp argmax (tie -> smaller index), carrying coords
#pragma unroll
        for (int off = 16; off > 0; off >>= 1) {
            float ov = __shfl_down_sync(0xffffffffu, bv, off);
            int   oi = __shfl_down_sync(0xffffffffu, bi, off);
            float ox = __shfl_down_sync(0xffffffffu, bx, off);
            float oy = __shfl_down_sync(0xffffffffu, by, off);
            float oz = __shfl_down_sync(0xffffffffu, bz, off);
            if (ov > bv || (ov == bv && oi < bi)) {
                bv = ov; bi = oi; bx = ox; by = oy; bz = oz;
            }
        }
        if (lane == 0) {
            s_wv[w] = bv; s_wi[w] = bi; s_wx[w] = bx; s_wy[w] = by; s_wz[w] = bz;
        }
        __syncthreads();
        const int par = s & 1;
        if (w == 0) {
            bv = s_wv[lane]; bi = s_wi[lane];
            bx = s_wx[lane]; by = s_wy[lane]; bz = s_wz[lane];
#pragma unroll
            for (int off = 16; off > 0; off >>= 1) {
                float ov = __shfl_down_sync(0xffffffffu, bv, off);
                int   oi = __shfl_down_sync(0xffffffffu, bi, off);
                float ox = __shfl_down_sync(0xffffffffu, bx, off);
                float oy = __shfl_down_sync(0xffffffffu, by, off);
                float oz = __shfl_down_sync(0xffffffffu, bz, off);
                if (ov > bv || (ov == bv && oi < bi)) {
                    bv = ov; bi = oi; bx = ox; by = oy; bz = oz;
                }
            }
            // broadcast winner to lanes, then lanes 0..7 store to peer=lane
            bv = __shfl_sync(0xffffffffu, bv, 0);
            bi = __shfl_sync(0xffffffffu, bi, 0);
            bx = __shfl_sync(0xffffffffu, bx, 0);
            by = __shfl_sync(0xffffffffu, by, 0);
            bz = __shfl_sync(0xffffffffu, bz, 0);
            if (lane < CL) {
                uint32_t peer = (uint32_t)lane;
                st_peer_f32((uint32_t)__cvta_generic_to_shared(&c_v[par][rank]), peer, bv);
                st_peer_s32((uint32_t)__cvta_generic_to_shared(&c_i[par][rank]), peer, bi);
                st_peer_f32((uint32_t)__cvta_generic_to_shared(&c_x[par][rank]), peer, bx);
                st_peer_f32((uint32_t)__cvta_generic_to_shared(&c_y[par][rank]), peer, by);
                st_peer_f32((uint32_t)__cvta_generic_to_shared(&c_z[par][rank]), peer, bz);
            }
        }
        asm volatile("barrier.cluster.arrive.aligned;" ::: "memory");
        asm volatile("barrier.cluster.wait.aligned;" ::: "memory");

        // every thread reduces the 8 candidates identically
        float gv = -1.0f, gx = 0.f, gy = 0.f, gz = 0.f;
        int gi = 0;
#pragma unroll
        for (int p = 0; p < CL; p++) {
            float v = c_v[par][p];
            int   i = c_i[par][p];
            if (v > gv || (v == gv && i < gi)) {
                gv = v; gi = i;
                gx = c_x[par][p]; gy = c_y[par][p]; gz = c_z[par][p];
            }
        }
        qx = gx; qy = gy; qz = gz;
    }
}

// ---------------- ball query: one warp per query, first-32-by-index ----------------
__global__ void ball_kernel(const float* __restrict__ xyz,
                            const float* __restrict__ samp) {
    const int warp = (int)((blockIdx.x * blockDim.x + threadIdx.x) >> 5);
    const int lane = threadIdx.x & 31;
    if (warp >= BATCH * N_SAMP) return;
    const int b = warp >> 10;  // 1024 samples per batch
    const float* q = samp + (size_t)warp * 3;
    const float qx = q[0], qy = q[1], qz = q[2];
    const float* __restrict__ X = xyz + (size_t)b * N_PTS * 3;
    int* out = g_nidx + (size_t)warp * K_NEI;

    out[lane] = -1;  // default padding
    int cnt = 0;
    const float R2 = 0.04f;  // f32(0.04): matches JAX weak-typed radius*radius
    for (int base = 0; base < N_PTS && cnt < K_NEI; base += 32) {
        const int i = base + lane;
        float dx = __fsub_rn(qx, X[3 * i + 0]);
        float dy = __fsub_rn(qy, X[3 * i + 1]);
        float dz = __fsub_rn(qz, X[3 * i + 2]);
        float d2 = __fadd_rn(__fadd_rn(__fmul_rn(dx, dx), __fmul_rn(dy, dy)),
                             __fmul_rn(dz, dz));
        const bool in = d2 < R2;
        const unsigned m = __ballot_sync(0xffffffffu, in);
        if (in) {
            int r = cnt + __popc(m & ((1u << lane) - 1u));
            if (r < K_NEI) out[r] = i;
        }
        cnt += __popc(m);
    }
}

// ---------------- gather: one warp per (b,s,k) row, 128 floats ----------------
__global__ void gather_kernel(const float* __restrict__ feat,
                              float* __restrict__ out_feat) {
    const int warp = (int)((blockIdx.x * blockDim.x + threadIdx.x) >> 5);
    const int lane = threadIdx.x & 31;
    if (warp >= BATCH * N_SAMP * K_NEI) return;
    const int b = warp >> 15;  // 1024*32 rows per batch
    int idx = g_nidx[warp];
    int row = (idx < 0) ? N_SAMP : idx;  // -1 -> feat[:, 1024, :]
    const float4* src = (const float4*)(feat + ((size_t)b * N_PTS + row) * C_FEAT);
    float4* dst = (float4*)(out_feat + (size_t)warp * C_FEAT);
    dst[lane] = src[lane];
}

extern "C" void kernel_launch(void* const* d_in, const int* in_sizes, int n_in,
                              void* d_out, int out_size) {
    const float* xyz  = (const float*)d_in[0];
    const float* feat = (const float*)d_in[1];
    if (n_in >= 2 && in_sizes[0] != BATCH * N_PTS * 3) {  // defensive: identify by size
        xyz  = (const float*)d_in[1];
        feat = (const float*)d_in[0];
    }
    float* out = (float*)d_out;
    float* out_feat = out + (size_t)BATCH * N_SAMP * 3;

    fps_kernel<<<BATCH * CL, TPB>>>(xyz, out);

    const int ball_threads = BATCH * N_SAMP * 32;            // one warp/query
    ball_kernel<<<ball_threads / 256, 256>>>(xyz, out);

    const int gath_threads = BATCH * N_SAMP * K_NEI * 32;    // one warp/row
    gather_kernel<<<gath_threads / 256, 256>>>(feat, out_feat);
}

// round 4
// speedup vs baseline: 1.6166x; 1.6166x over previous
#include <cuda_runtime.h>
#include <cstdint>

#define BATCH  4
#define N_PTS  16384
#define N_SAMP 1024
#define K_NEI  32
#define C_FEAT 128
#define CL     8               // cluster size (CTAs per batch)
#define TPB    1024
#define PPT    2               // N_PTS / (CL*TPB)
#define FULL   0xffffffffu
#define IDX_INF 0x7fffffffu

// scratch: neighbor indices (device global -> no allocation)
__device__ int g_nidx[BATCH * N_SAMP * K_NEI];

// ---------------- threefry2x32 (JAX-compatible, both output words) ----------------
__device__ __forceinline__ uint32_t rotl32(uint32_t x, int r) {
    return (x << r) | (x >> (32 - r));
}

__device__ __forceinline__ void threefry2x32(uint32_t k0, uint32_t k1,
                                             uint32_t x0, uint32_t x1,
                                             uint32_t& o0, uint32_t& o1) {
    uint32_t ks2 = k0 ^ k1 ^ 0x1BD11BDAu;
    x0 += k0; x1 += k1;
#define TF_RND(r) { x0 += x1; x1 = rotl32(x1, (r)); x1 ^= x0; }
    TF_RND(13) TF_RND(15) TF_RND(26) TF_RND(6)   x0 += k1;  x1 += ks2 + 1u;
    TF_RND(17) TF_RND(29) TF_RND(16) TF_RND(24)  x0 += ks2; x1 += k0 + 2u;
    TF_RND(13) TF_RND(15) TF_RND(26) TF_RND(6)   x0 += k0;  x1 += k1 + 3u;
    TF_RND(17) TF_RND(29) TF_RND(16) TF_RND(24)  x0 += k1;  x1 += ks2 + 4u;
    TF_RND(13) TF_RND(15) TF_RND(26) TF_RND(6)   x0 += ks2; x1 += k0 + 5u;
#undef TF_RND
    o0 = x0; o1 = x1;
}

// start index for batch b (JAX threefry_partitionable=True path):
//   k1,k2 = split(key(42)); bits_b = o0^o1 of tf2x32(k2,(0,b)); start = bits & 16383
__device__ __forceinline__ int jax_start_idx(int b) {
    uint32_t k2a, k2b;
    threefry2x32(0u, 42u, 0u, 1u, k2a, k2b);
    uint32_t o0, o1;
    threefry2x32(k2a, k2b, 0u, (uint32_t)b, o0, o1);
    return (int)((o0 ^ o1) & (uint32_t)(N_PTS - 1));
}

// ---------------- cluster DSMEM / mbarrier helpers ----------------
__device__ __forceinline__ void st_peer_v4(uint32_t laddr, uint32_t peer,
                                           uint32_t a, uint32_t b,
                                           uint32_t c, uint32_t d) {
    uint32_t r;
    asm volatile("mapa.shared::cluster.u32 %0, %1, %2;" : "=r"(r) : "r"(laddr), "r"(peer));
    asm volatile("st.shared::cluster.v4.b32 [%0], {%1,%2,%3,%4};"
                 :: "r"(r), "r"(a), "r"(b), "r"(c), "r"(d) : "memory");
}
__device__ __forceinline__ void st_peer_b32(uint32_t laddr, uint32_t peer, uint32_t v) {
    uint32_t r;
    asm volatile("mapa.shared::cluster.u32 %0, %1, %2;" : "=r"(r) : "r"(laddr), "r"(peer));
    asm volatile("st.shared::cluster.b32 [%0], %1;" :: "r"(r), "r"(v) : "memory");
}
__device__ __forceinline__ void mbar_arrive_peer(uint32_t lmbar, uint32_t peer) {
    uint32_t r;
    asm volatile("mapa.shared::cluster.u32 %0, %1, %2;" : "=r"(r) : "r"(lmbar), "r"(peer));
    asm volatile("mbarrier.arrive.release.cluster.shared::cluster.b64 _, [%0];"
                 :: "r"(r) : "memory");
}
__device__ __forceinline__ void mbar_wait(uint32_t mbar, uint32_t phase) {
    uint32_t done = 0;
    while (!done) {
        asm volatile(
            "{\n\t.reg .pred p;\n\t"
            "mbarrier.try_wait.parity.acquire.cluster.shared::cta.b64 p, [%1], %2, 0x989680;\n\t"
            "selp.b32 %0, 1, 0, p;\n\t}"
            : "=r"(done) : "r"(mbar), "r"(phase) : "memory");
    }
}

// ---------------- FPS: one 8-CTA cluster per batch ----------------
__global__ void __cluster_dims__(CL, 1, 1) fps_kernel(const float* __restrict__ xyz,
                                                      float* __restrict__ out_xyz) {
    const int b = blockIdx.x / CL;
    uint32_t rank;
    asm("mov.u32 %0, %%cluster_ctarank;" : "=r"(rank));
    const float* __restrict__ X = xyz + (size_t)b * N_PTS * 3;
    const int t = threadIdx.x;
    const int base = (int)rank * (TPB * PPT);
    const int w = t >> 5, lane = t & 31;

    // register-resident points + running min distance
    float px[PPT], py[PPT], pz[PPT], md[PPT];
#pragma unroll
    for (int j = 0; j < PPT; j++) {
        int i = base + j * TPB + t;
        px[j] = X[3 * i + 0];
        py[j] = X[3 * i + 1];
        pz[j] = X[3 * i + 2];
        md[j] = __int_as_float(0x7f800000);  // +inf
    }

    // per-warp candidates: {vbits, idx, x, y, z, pad[3]} 32B each
    __shared__ uint32_t s_w[32 * 8];
    // cross-CTA slots, double-buffered: s_c[buf][src][8] (32B each)
    __shared__ uint32_t s_c[2][CL][8];
    __shared__ unsigned long long s_mbar[2];

    if (t == 0) {
        asm volatile("mbarrier.init.shared.b64 [%0], %1;"
                     :: "r"((uint32_t)__cvta_generic_to_shared(&s_mbar[0])), "r"(CL) : "memory");
        asm volatile("mbarrier.init.shared.b64 [%0], %1;"
                     :: "r"((uint32_t)__cvta_generic_to_shared(&s_mbar[1])), "r"(CL) : "memory");
    }
    __syncthreads();
    asm volatile("barrier.cluster.arrive.aligned;" ::: "memory");
    asm volatile("barrier.cluster.wait.aligned;" ::: "memory");

    int cur = jax_start_idx(b);
    float qx = X[3 * cur + 0], qy = X[3 * cur + 1], qz = X[3 * cur + 2];

    for (int s = 0; ; s++) {
        if (rank == 0 && t == 0) {
            float* o = out_xyz + ((size_t)b * N_SAMP + s) * 3;
            o[0] = qx; o[1] = qy; o[2] = qz;
        }
        if (s == N_SAMP - 1) break;

        // ---- thread-local update + best (EXACT: no FMA, left-assoc sum) ----
        uint32_t bu = 0u; uint32_t bi = IDX_INF;
        float bx = 0.f, by = 0.f, bz = 0.f;
#pragma unroll
        for (int j = 0; j < PPT; j++) {
            float dx = __fsub_rn(px[j], qx);
            float dy = __fsub_rn(py[j], qy);
            float dz = __fsub_rn(pz[j], qz);
            float d2 = __fadd_rn(__fadd_rn(__fmul_rn(dx, dx), __fmul_rn(dy, dy)),
                                 __fmul_rn(dz, dz));
            float m = fminf(md[j], d2);
            md[j] = m;
            uint32_t mu = __float_as_uint(m);  // m >= 0 -> IEEE order == u32 order
            if (mu > bu) {                     // strict > keeps smaller index (j asc)
                bu = mu; bi = (uint32_t)(base + j * TPB + t);
                bx = px[j]; by = py[j]; bz = pz[j];
            }
        }
        // ---- warp argmax via redux (exact, min-index ties) ----
        uint32_t wm = __reduce_max_sync(FULL, bu);
        uint32_t wi = __reduce_min_sync(FULL, (bu == wm) ? bi : IDX_INF);
        if (bu == wm && bi == wi) {            // unique winning lane writes slot
            uint32_t* sw = &s_w[w * 8];
            sw[0] = wm; sw[1] = wi;
            sw[2] = __float_as_uint(bx);
            sw[3] = __float_as_uint(by);
            sw[4] = __float_as_uint(bz);
        }
        __syncthreads();

        const int buf = s & 1;
        if (w == 0) {
            // reduce 32 per-warp candidates (all 32 lanes valid)
            const uint32_t* sw = &s_w[lane * 8];
            uint32_t v = sw[0], i = sw[1];
            uint32_t x = sw[2], y = sw[3], z = sw[4];
            uint32_t cm = __reduce_max_sync(FULL, v);
            uint32_t ci = __reduce_min_sync(FULL, (v == cm) ? i : IDX_INF);
            uint32_t mk = __ballot_sync(FULL, v == cm && i == ci);
            int ls = __ffs(mk) - 1;
            uint32_t cx = __shfl_sync(FULL, x, ls);
            uint32_t cy = __shfl_sync(FULL, y, ls);
            uint32_t cz = __shfl_sync(FULL, z, ls);
            if (lane < CL) {  // lane l -> peer l: store CTA candidate + arrive
                uint32_t slot = (uint32_t)__cvta_generic_to_shared(&s_c[buf][rank][0]);
                st_peer_v4(slot, (uint32_t)lane, cm, ci, cx, cy);
                st_peer_b32(slot + 16, (uint32_t)lane, cz);
                mbar_arrive_peer((uint32_t)__cvta_generic_to_shared(&s_mbar[buf]),
                                 (uint32_t)lane);
            }
        }

        // ---- all warps: wait for 8 arrivals, reduce 8 slots ----
        mbar_wait((uint32_t)__cvta_generic_to_shared(&s_mbar[buf]), (uint32_t)((s >> 1) & 1));
        uint32_t v = 0u, i = IDX_INF, x = 0u, y = 0u, z = 0u;
        if (lane < CL) {
            const uint32_t* sc = &s_c[buf][lane][0];
            v = sc[0]; i = sc[1]; x = sc[2]; y = sc[3]; z = sc[4];
        }
        uint32_t gm = __reduce_max_sync(FULL, v);
        uint32_t gi = __reduce_min_sync(FULL, (v == gm) ? i : IDX_INF);
        uint32_t mk = __ballot_sync(FULL, v == gm && i == gi);
        int ls = __ffs(mk) - 1;
        qx = __uint_as_float(__shfl_sync(FULL, x, ls));
        qy = __uint_as_float(__shfl_sync(FULL, y, ls));
        qz = __uint_as_float(__shfl_sync(FULL, z, ls));
    }

    // drain: no CTA exits while peers may still target its smem
    asm volatile("barrier.cluster.arrive.aligned;" ::: "memory");
    asm volatile("barrier.cluster.wait.aligned;" ::: "memory");
}

// ---------------- ball query: one warp per query, first-32-by-index ----------------
__global__ void ball_kernel(const float* __restrict__ xyz,
                            const float* __restrict__ samp) {
    const int warp = (int)((blockIdx.x * blockDim.x + threadIdx.x) >> 5);
    const int lane = threadIdx.x & 31;
    if (warp >= BATCH * N_SAMP) return;
    const int b = warp >> 10;  // 1024 samples per batch
    const float* q = samp + (size_t)warp * 3;
    const float qx = q[0], qy = q[1], qz = q[2];
    const float* __restrict__ X = xyz + (size_t)b * N_PTS * 3;
    int* out = g_nidx + (size_t)warp * K_NEI;

    out[lane] = -1;  // default padding
    int cnt = 0;
    const float R2 = 0.04f;  // f32(0.04): matches JAX weak-typed radius*radius
    for (int base = 0; base < N_PTS && cnt < K_NEI; base += 32) {
        const int i = base + lane;
        float dx = __fsub_rn(qx, X[3 * i + 0]);
        float dy = __fsub_rn(qy, X[3 * i + 1]);
        float dz = __fsub_rn(qz, X[3 * i + 2]);
        float d2 = __fadd_rn(__fadd_rn(__fmul_rn(dx, dx), __fmul_rn(dy, dy)),
                             __fmul_rn(dz, dz));
        const bool in = d2 < R2;
        const unsigned m = __ballot_sync(0xffffffffu, in);
        if (in) {
            int r = cnt + __popc(m & ((1u << lane) - 1u));
            if (r < K_NEI) out[r] = i;
        }
        cnt += __popc(m);
    }
}

// ---------------- gather: one warp per (b,s,k) row, 128 floats ----------------
__global__ void gather_kernel(const float* __restrict__ feat,
                              float* __restrict__ out_feat) {
    const int warp = (int)((blockIdx.x * blockDim.x + threadIdx.x) >> 5);
    const int lane = threadIdx.x & 31;
    if (warp >= BATCH * N_SAMP * K_NEI) return;
    const int b = warp >> 15;  // 1024*32 rows per batch
    int idx = g_nidx[warp];
    int row = (idx < 0) ? N_SAMP : idx;  // -1 -> feat[:, 1024, :]
    const float4* src = (const float4*)(feat + ((size_t)b * N_PTS + row) * C_FEAT);
    float4* dst = (float4*)(out_feat + (size_t)warp * C_FEAT);
    dst[lane] = src[lane];
}

extern "C" void kernel_launch(void* const* d_in, const int* in_sizes, int n_in,
                              void* d_out, int out_size) {
    const float* xyz  = (const float*)d_in[0];
    const float* feat = (const float*)d_in[1];
    if (n_in >= 2 && in_sizes[0] != BATCH * N_PTS * 3) {  // defensive: identify by size
        xyz  = (const float*)d_in[1];
        feat = (const float*)d_in[0];
    }
    float* out = (float*)d_out;
    float* out_feat = out + (size_t)BATCH * N_SAMP * 3;

    fps_kernel<<<BATCH * CL, TPB>>>(xyz, out);

    const int ball_threads = BATCH * N_SAMP * 32;            // one warp/query
    ball_kernel<<<ball_threads / 256, 256>>>(xyz, out);

    const int gath_threads = BATCH * N_SAMP * K_NEI * 32;    // one warp/row
    gather_kernel<<<gath_threads / 256, 256>>>(feat, out_feat);
}

// round 5
// speedup vs baseline: 2.1037x; 1.3013x over previous
#include <cuda_runtime.h>
#include <cstdint>

#define BATCH  4
#define N_PTS  16384
#define N_SAMP 1024
#define K_NEI  32
#define C_FEAT 128
#define CL     8               // cluster size (CTAs per batch)
#define TPB    1024
#define PPT    2               // N_PTS / (CL*TPB)
#define FULL   0xffffffffu
#define IDX_INF 0x7fffffffu
#define TX_BYTES (CL * 20u)    // 8 producers x (16B v4 + 4B b32)

// scratch: neighbor indices (device global -> no allocation)
__device__ int g_nidx[BATCH * N_SAMP * K_NEI];

// ---------------- threefry2x32 (JAX-compatible, both output words) ----------------
__device__ __forceinline__ uint32_t rotl32(uint32_t x, int r) {
    return (x << r) | (x >> (32 - r));
}

__device__ __forceinline__ void threefry2x32(uint32_t k0, uint32_t k1,
                                             uint32_t x0, uint32_t x1,
                                             uint32_t& o0, uint32_t& o1) {
    uint32_t ks2 = k0 ^ k1 ^ 0x1BD11BDAu;
    x0 += k0; x1 += k1;
#define TF_RND(r) { x0 += x1; x1 = rotl32(x1, (r)); x1 ^= x0; }
    TF_RND(13) TF_RND(15) TF_RND(26) TF_RND(6)   x0 += k1;  x1 += ks2 + 1u;
    TF_RND(17) TF_RND(29) TF_RND(16) TF_RND(24)  x0 += ks2; x1 += k0 + 2u;
    TF_RND(13) TF_RND(15) TF_RND(26) TF_RND(6)   x0 += k0;  x1 += k1 + 3u;
    TF_RND(17) TF_RND(29) TF_RND(16) TF_RND(24)  x0 += k1;  x1 += ks2 + 4u;
    TF_RND(13) TF_RND(15) TF_RND(26) TF_RND(6)   x0 += ks2; x1 += k0 + 5u;
#undef TF_RND
    o0 = x0; o1 = x1;
}

// start index for batch b (JAX threefry_partitionable=True path):
//   k1,k2 = split(key(42)); bits_b = o0^o1 of tf2x32(k2,(0,b)); start = bits & 16383
__device__ __forceinline__ int jax_start_idx(int b) {
    uint32_t k2a, k2b;
    threefry2x32(0u, 42u, 0u, 1u, k2a, k2b);
    uint32_t o0, o1;
    threefry2x32(k2a, k2b, 0u, (uint32_t)b, o0, o1);
    return (int)((o0 ^ o1) & (uint32_t)(N_PTS - 1));
}

// ---------------- cluster DSMEM / mbarrier helpers ----------------
// fused store+signal: data lands in peer smem, tx bytes credited on peer's mbar
__device__ __forceinline__ void st_async_peer_v4(uint32_t laddr, uint32_t lmbar,
                                                 uint32_t peer,
                                                 uint32_t a, uint32_t b,
                                                 uint32_t c, uint32_t d) {
    uint32_t ra, rm;
    asm volatile("mapa.shared::cluster.u32 %0, %1, %2;" : "=r"(ra) : "r"(laddr), "r"(peer));
    asm volatile("mapa.shared::cluster.u32 %0, %1, %2;" : "=r"(rm) : "r"(lmbar), "r"(peer));
    asm volatile("st.async.shared::cluster.mbarrier::complete_tx::bytes.v4.b32 "
                 "[%0], {%1,%2,%3,%4}, [%5];"
                 :: "r"(ra), "r"(a), "r"(b), "r"(c), "r"(d), "r"(rm) : "memory");
}
__device__ __forceinline__ void st_async_peer_b32(uint32_t laddr, uint32_t lmbar,
                                                  uint32_t peer, uint32_t v) {
    uint32_t ra, rm;
    asm volatile("mapa.shared::cluster.u32 %0, %1, %2;" : "=r"(ra) : "r"(laddr), "r"(peer));
    asm volatile("mapa.shared::cluster.u32 %0, %1, %2;" : "=r"(rm) : "r"(lmbar), "r"(peer));
    asm volatile("st.async.shared::cluster.mbarrier::complete_tx::bytes.b32 "
                 "[%0], %1, [%2];"
                 :: "r"(ra), "r"(v), "r"(rm) : "memory");
}
__device__ __forceinline__ void mbar_expect_tx(uint32_t mbar, uint32_t bytes) {
    asm volatile("mbarrier.arrive.expect_tx.shared.b64 _, [%0], %1;"
                 :: "r"(mbar), "r"(bytes) : "memory");
}
__device__ __forceinline__ void mbar_wait(uint32_t mbar, uint32_t phase) {
    uint32_t done = 0;
    while (!done) {
        asm volatile(
            "{\n\t.reg .pred p;\n\t"
            "mbarrier.try_wait.parity.acquire.cluster.shared::cta.b64 p, [%1], %2, 0x989680;\n\t"
            "selp.b32 %0, 1, 0, p;\n\t}"
            : "=r"(done) : "r"(mbar), "r"(phase) : "memory");
    }
}

// ---------------- FPS: one 8-CTA cluster per batch ----------------
__global__ void __cluster_dims__(CL, 1, 1) fps_kernel(const float* __restrict__ xyz,
                                                      float* __restrict__ out_xyz) {
    const int b = blockIdx.x / CL;
    uint32_t rank;
    asm("mov.u32 %0, %%cluster_ctarank;" : "=r"(rank));
    const float* __restrict__ X = xyz + (size_t)b * N_PTS * 3;
    const int t = threadIdx.x;
    const int base = (int)rank * (TPB * PPT);
    const int w = t >> 5, lane = t & 31;

    // register-resident points + running min distance
    float px[PPT], py[PPT], pz[PPT], md[PPT];
#pragma unroll
    for (int j = 0; j < PPT; j++) {
        int i = base + j * TPB + t;
        px[j] = X[3 * i + 0];
        py[j] = X[3 * i + 1];
        pz[j] = X[3 * i + 2];
        md[j] = __int_as_float(0x7f800000);  // +inf
    }

    // per-warp candidates: stride 5 words (gcd(5,32)=1 -> conflict-free LDS)
    __shared__ uint32_t s_w[32 * 5];
    // cross-CTA slots, double-buffered: s_c[buf][src][8] (16B-aligned for v4 st.async)
    __shared__ uint32_t s_c[2][CL][8];
    __shared__ unsigned long long s_mbar[2];

    if (t == 0) {
        asm volatile("mbarrier.init.shared.b64 [%0], %1;"
                     :: "r"((uint32_t)__cvta_generic_to_shared(&s_mbar[0])), "r"(1) : "memory");
        asm volatile("mbarrier.init.shared.b64 [%0], %1;"
                     :: "r"((uint32_t)__cvta_generic_to_shared(&s_mbar[1])), "r"(1) : "memory");
    }
    __syncthreads();
    asm volatile("barrier.cluster.arrive.aligned;" ::: "memory");
    asm volatile("barrier.cluster.wait.aligned;" ::: "memory");

    int cur = jax_start_idx(b);
    float qx = X[3 * cur + 0], qy = X[3 * cur + 1], qz = X[3 * cur + 2];

    for (int s = 0; ; s++) {
        if (rank == 0 && t == 0) {
            float* o = out_xyz + ((size_t)b * N_SAMP + s) * 3;
            o[0] = qx; o[1] = qy; o[2] = qz;
        }
        if (s == N_SAMP - 1) break;

        const int buf = s & 1;
        // arm this phase's mbar early (pending arrival=1 until this post, so no
        // premature flip even if producer bytes land first; negative tx is legal)
        if (t == 0)
            mbar_expect_tx((uint32_t)__cvta_generic_to_shared(&s_mbar[buf]), TX_BYTES);

        // ---- thread-local update + best (EXACT: no FMA, left-assoc sum) ----
        uint32_t bu = 0u; uint32_t bi = IDX_INF;
#pragma unroll
        for (int j = 0; j < PPT; j++) {
            float dx = __fsub_rn(px[j], qx);
            float dy = __fsub_rn(py[j], qy);
            float dz = __fsub_rn(pz[j], qz);
            float d2 = __fadd_rn(__fadd_rn(__fmul_rn(dx, dx), __fmul_rn(dy, dy)),
                                 __fmul_rn(dz, dz));
            float m = fminf(md[j], d2);
            md[j] = m;
            uint32_t mu = __float_as_uint(m);  // m >= 0 -> IEEE order == u32 order
            if (mu > bu) {                     // strict > keeps smaller index (j asc)
                bu = mu; bi = (uint32_t)(base + j * TPB + t);
            }
        }
        // ---- warp argmax via redux (exact, min-index ties) ----
        uint32_t wm = __reduce_max_sync(FULL, bu);
        uint32_t wi = __reduce_min_sync(FULL, (bu == wm) ? bi : IDX_INF);
        if (bu == wm && bi == wi) {            // unique winning lane writes slot
            int jw = (bi - (uint32_t)(base + t)) >= (uint32_t)TPB;  // PPT==2
            uint32_t* sw = &s_w[w * 5];
            sw[0] = wm; sw[1] = wi;
            sw[2] = __float_as_uint(jw ? px[1] : px[0]);
            sw[3] = __float_as_uint(jw ? py[1] : py[0]);
            sw[4] = __float_as_uint(jw ? pz[1] : pz[0]);
        }
        __syncthreads();

        if (w == 0) {
            // reduce 32 per-warp candidates (all 32 lanes valid)
            const uint32_t* sw = &s_w[lane * 5];
            uint32_t v = sw[0], i = sw[1];
            uint32_t x = sw[2], y = sw[3], z = sw[4];
            uint32_t cm = __reduce_max_sync(FULL, v);
            uint32_t ci = __reduce_min_sync(FULL, (v == cm) ? i : IDX_INF);
            uint32_t mk = __ballot_sync(FULL, v == cm && i == ci);
            int ls = __ffs(mk) - 1;
            uint32_t cx = __shfl_sync(FULL, x, ls);
            uint32_t cy = __shfl_sync(FULL, y, ls);
            uint32_t cz = __shfl_sync(FULL, z, ls);
            if (lane < CL) {  // lane l -> peer l: fused store+signal (1 hop)
                uint32_t slot = (uint32_t)__cvta_generic_to_shared(&s_c[buf][rank][0]);
                uint32_t mb   = (uint32_t)__cvta_generic_to_shared(&s_mbar[buf]);
                st_async_peer_v4(slot, mb, (uint32_t)lane, cm, ci, cx, cy);
                st_async_peer_b32(slot + 16, mb, (uint32_t)lane, cz);
            }
        }

        // ---- all warps: wait for 160 tx bytes, reduce 8 slots ----
        mbar_wait((uint32_t)__cvta_generic_to_shared(&s_mbar[buf]), (uint32_t)((s >> 1) & 1));
        uint32_t v = 0u, i = IDX_INF, x = 0u, y = 0u, z = 0u;
        if (lane < CL) {
            const uint32_t* sc = &s_c[buf][lane][0];
            v = sc[0]; i = sc[1]; x = sc[2]; y = sc[3]; z = sc[4];
        }
        uint32_t gm = __reduce_max_sync(FULL, v);
        uint32_t gi = __reduce_min_sync(FULL, (v == gm) ? i : IDX_INF);
        uint32_t mk = __ballot_sync(FULL, v == gm && i == gi);
        int ls = __ffs(mk) - 1;
        qx = __uint_as_float(__shfl_sync(FULL, x, ls));
        qy = __uint_as_float(__shfl_sync(FULL, y, ls));
        qz = __uint_as_float(__shfl_sync(FULL, z, ls));
    }

    // drain: no CTA exits while peers may still target its smem
    asm volatile("barrier.cluster.arrive.aligned;" ::: "memory");
    asm volatile("barrier.cluster.wait.aligned;" ::: "memory");
}

// ---------------- ball query: one warp per query, first-32-by-index ----------------
__global__ void ball_kernel(const float* __restrict__ xyz,
                            const float* __restrict__ samp) {
    const int warp = (int)((blockIdx.x * blockDim.x + threadIdx.x) >> 5);
    const int lane = threadIdx.x & 31;
    if (warp >= BATCH * N_SAMP) return;
    const int b = warp >> 10;  // 1024 samples per batch
    const float* q = samp + (size_t)warp * 3;
    const float qx = q[0], qy = q[1], qz = q[2];
    const float* __restrict__ X = xyz + (size_t)b * N_PTS * 3;
    int* out = g_nidx + (size_t)warp * K_NEI;

    out[lane] = -1;  // default padding
    int cnt = 0;
    const float R2 = 0.04f;  // f32(0.04): matches JAX weak-typed radius*radius
    for (int base = 0; base < N_PTS && cnt < K_NEI; base += 32) {
        const int i = base + lane;
        float dx = __fsub_rn(qx, X[3 * i + 0]);
        float dy = __fsub_rn(qy, X[3 * i + 1]);
        float dz = __fsub_rn(qz, X[3 * i + 2]);
        float d2 = __fadd_rn(__fadd_rn(__fmul_rn(dx, dx), __fmul_rn(dy, dy)),
                             __fmul_rn(dz, dz));
        const bool in = d2 < R2;
        const unsigned m = __ballot_sync(0xffffffffu, in);
        if (in) {
            int r = cnt + __popc(m & ((1u << lane) - 1u));
            if (r < K_NEI) out[r] = i;
        }
        cnt += __popc(m);
    }
}

// ---------------- gather: one warp per (b,s,k) row, 128 floats ----------------
__global__ void gather_kernel(const float* __restrict__ feat,
                              float* __restrict__ out_feat) {
    const int warp = (int)((blockIdx.x * blockDim.x + threadIdx.x) >> 5);
    const int lane = threadIdx.x & 31;
    if (warp >= BATCH * N_SAMP * K_NEI) return;
    const int b = warp >> 15;  // 1024*32 rows per batch
    int idx = g_nidx[warp];
    int row = (idx < 0) ? N_SAMP : idx;  // -1 -> feat[:, 1024, :]
    const float4* src = (const float4*)(feat + ((size_t)b * N_PTS + row) * C_FEAT);
    float4* dst = (float4*)(out_feat + (size_t)warp * C_FEAT);
    dst[lane] = src[lane];
}

extern "C" void kernel_launch(void* const* d_in, const int* in_sizes, int n_in,
                              void* d_out, int out_size) {
    const float* xyz  = (const float*)d_in[0];
    const float* feat = (const float*)d_in[1];
    if (n_in >= 2 && in_sizes[0] != BATCH * N_PTS * 3) {  // defensive: identify by size
        xyz  = (const float*)d_in[1];
        feat = (const float*)d_in[0];
    }
    float* out = (float*)d_out;
    float* out_feat = out + (size_t)BATCH * N_SAMP * 3;

    fps_kernel<<<BATCH * CL, TPB>>>(xyz, out);

    const int ball_threads = BATCH * N_SAMP * 32;            // one warp/query
    ball_kernel<<<ball_threads / 256, 256>>>(xyz, out);

    const int gath_threads = BATCH * N_SAMP * K_NEI * 32;    // one warp/row
    gather_kernel<<<gath_threads / 256, 256>>>(feat, out_feat);
}

// round 6
// speedup vs baseline: 2.8124x; 1.3369x over previous
#include <cuda_runtime.h>
#include <cstdint>

#define BATCH  4
#define N_PTS  16384
#define N_SAMP 1024
#define K_NEI  32
#define C_FEAT 128
#define CL     8               // cluster size (CTAs per batch)
#define TPB    256
#define NWARP  (TPB / 32)      // 8 warps per CTA
#define PPT    8               // N_PTS / (CL*TPB)
#define NSLOT  (CL * NWARP)    // 64 cluster-wide warp candidates
#define FULL   0xffffffffu
#define IDX_INF 0x7fffffffu
#define TX_BYTES (NSLOT * 20u) // 64 producers x (16B v4 + 4B b32)

// scratch: neighbor indices (device global -> no allocation)
__device__ int g_nidx[BATCH * N_SAMP * K_NEI];

// ---------------- threefry2x32 (JAX-compatible, both output words) ----------------
__device__ __forceinline__ uint32_t rotl32(uint32_t x, int r) {
    return (x << r) | (x >> (32 - r));
}

__device__ __forceinline__ void threefry2x32(uint32_t k0, uint32_t k1,
                                             uint32_t x0, uint32_t x1,
                                             uint32_t& o0, uint32_t& o1) {
    uint32_t ks2 = k0 ^ k1 ^ 0x1BD11BDAu;
    x0 += k0; x1 += k1;
#define TF_RND(r) { x0 += x1; x1 = rotl32(x1, (r)); x1 ^= x0; }
    TF_RND(13) TF_RND(15) TF_RND(26) TF_RND(6)   x0 += k1;  x1 += ks2 + 1u;
    TF_RND(17) TF_RND(29) TF_RND(16) TF_RND(24)  x0 += ks2; x1 += k0 + 2u;
    TF_RND(13) TF_RND(15) TF_RND(26) TF_RND(6)   x0 += k0;  x1 += k1 + 3u;
    TF_RND(17) TF_RND(29) TF_RND(16) TF_RND(24)  x0 += k1;  x1 += ks2 + 4u;
    TF_RND(13) TF_RND(15) TF_RND(26) TF_RND(6)   x0 += ks2; x1 += k0 + 5u;
#undef TF_RND
    o0 = x0; o1 = x1;
}

// start index for batch b (JAX threefry_partitionable=True path):
//   k1,k2 = split(key(42)); bits_b = o0^o1 of tf2x32(k2,(0,b)); start = bits & 16383
__device__ __forceinline__ int jax_start_idx(int b) {
    uint32_t k2a, k2b;
    threefry2x32(0u, 42u, 0u, 1u, k2a, k2b);
    uint32_t o0, o1;
    threefry2x32(k2a, k2b, 0u, (uint32_t)b, o0, o1);
    return (int)((o0 ^ o1) & (uint32_t)(N_PTS - 1));
}

// ---------------- cluster DSMEM / mbarrier helpers ----------------
__device__ __forceinline__ void st_async_peer_v4(uint32_t laddr, uint32_t lmbar,
                                                 uint32_t peer,
                                                 uint32_t a, uint32_t b,
                                                 uint32_t c, uint32_t d) {
    uint32_t ra, rm;
    asm volatile("mapa.shared::cluster.u32 %0, %1, %2;" : "=r"(ra) : "r"(laddr), "r"(peer));
    asm volatile("mapa.shared::cluster.u32 %0, %1, %2;" : "=r"(rm) : "r"(lmbar), "r"(peer));
    asm volatile("st.async.shared::cluster.mbarrier::complete_tx::bytes.v4.b32 "
                 "[%0], {%1,%2,%3,%4}, [%5];"
                 :: "r"(ra), "r"(a), "r"(b), "r"(c), "r"(d), "r"(rm) : "memory");
}
__device__ __forceinline__ void st_async_peer_b32(uint32_t laddr, uint32_t lmbar,
                                                  uint32_t peer, uint32_t v) {
    uint32_t ra, rm;
    asm volatile("mapa.shared::cluster.u32 %0, %1, %2;" : "=r"(ra) : "r"(laddr), "r"(peer));
    asm volatile("mapa.shared::cluster.u32 %0, %1, %2;" : "=r"(rm) : "r"(lmbar), "r"(peer));
    asm volatile("st.async.shared::cluster.mbarrier::complete_tx::bytes.b32 "
                 "[%0], %1, [%2];"
                 :: "r"(ra), "r"(v), "r"(rm) : "memory");
}
__device__ __forceinline__ void mbar_expect_tx(uint32_t mbar, uint32_t bytes) {
    asm volatile("mbarrier.arrive.expect_tx.shared.b64 _, [%0], %1;"
                 :: "r"(mbar), "r"(bytes) : "memory");
}
__device__ __forceinline__ void mbar_wait(uint32_t mbar, uint32_t phase) {
    uint32_t done = 0;
    while (!done) {
        asm volatile(
            "{\n\t.reg .pred p;\n\t"
            "mbarrier.try_wait.parity.acquire.cluster.shared::cta.b64 p, [%1], %2, 0x989680;\n\t"
            "selp.b32 %0, 1, 0, p;\n\t}"
            : "=r"(done) : "r"(mbar), "r"(phase) : "memory");
    }
}

// ---------------- FPS: one 8-CTA cluster per batch ----------------
__global__ void __cluster_dims__(CL, 1, 1) fps_kernel(const float* __restrict__ xyz,
                                                      float* __restrict__ out_xyz) {
    const int b = blockIdx.x / CL;
    uint32_t rank;
    asm("mov.u32 %0, %%cluster_ctarank;" : "=r"(rank));
    const float* __restrict__ X = xyz + (size_t)b * N_PTS * 3;
    const int t = threadIdx.x;
    const int base = (int)rank * (TPB * PPT);
    const int w = t >> 5, lane = t & 31;

    // register-resident points + running min distance
    float px[PPT], py[PPT], pz[PPT], md[PPT];
#pragma unroll
    for (int j = 0; j < PPT; j++) {
        int i = base + j * TPB + t;
        px[j] = X[3 * i + 0];
        py[j] = X[3 * i + 1];
        pz[j] = X[3 * i + 2];
        md[j] = __int_as_float(0x7f800000);  // +inf
    }

    // cluster-wide warp candidates, double-buffered: 32B/slot (16B-aligned)
    __shared__ uint32_t s_c[2][NSLOT][8];
    __shared__ unsigned long long s_mbar[2];

    if (t == 0) {
        asm volatile("mbarrier.init.shared.b64 [%0], %1;"
                     :: "r"((uint32_t)__cvta_generic_to_shared(&s_mbar[0])), "r"(1) : "memory");
        asm volatile("mbarrier.init.shared.b64 [%0], %1;"
                     :: "r"((uint32_t)__cvta_generic_to_shared(&s_mbar[1])), "r"(1) : "memory");
    }
    __syncthreads();
    asm volatile("barrier.cluster.arrive.aligned;" ::: "memory");
    asm volatile("barrier.cluster.wait.aligned;" ::: "memory");

    int cur = jax_start_idx(b);
    float qx = X[3 * cur + 0], qy = X[3 * cur + 1], qz = X[3 * cur + 2];

    for (int s = 0; ; s++) {
        if (rank == 0 && t == 0) {
            float* o = out_xyz + ((size_t)b * N_SAMP + s) * 3;
            o[0] = qx; o[1] = qy; o[2] = qz;
        }
        if (s == N_SAMP - 1) break;

        const int buf = s & 1;
        // arm this phase's mbar (arrival count 1 = this arrive.expect_tx, so the
        // phase cannot flip before this post even if producer bytes land first)
        if (t == 0)
            mbar_expect_tx((uint32_t)__cvta_generic_to_shared(&s_mbar[buf]), TX_BYTES);

        // ---- thread-local update + best (EXACT: no FMA, left-assoc sum) ----
        uint32_t bu = 0u; uint32_t bi = IDX_INF;
        float bx = 0.f, by = 0.f, bz = 0.f;
#pragma unroll
        for (int j = 0; j < PPT; j++) {
            float dx = __fsub_rn(px[j], qx);
            float dy = __fsub_rn(py[j], qy);
            float dz = __fsub_rn(pz[j], qz);
            float d2 = __fadd_rn(__fadd_rn(__fmul_rn(dx, dx), __fmul_rn(dy, dy)),
                                 __fmul_rn(dz, dz));
            float m = fminf(md[j], d2);
            md[j] = m;
            uint32_t mu = __float_as_uint(m);  // m >= 0 -> IEEE order == u32 order
            if (mu > bu) {                     // strict > keeps smaller index (j asc)
                bu = mu; bi = (uint32_t)(base + j * TPB + t);
                bx = px[j]; by = py[j]; bz = pz[j];
            }
        }
        // ---- warp argmax via redux (exact, min-index ties) ----
        uint32_t wm = __reduce_max_sync(FULL, bu);
        uint32_t wi = __reduce_min_sync(FULL, (bu == wm) ? bi : IDX_INF);
        uint32_t mk = __ballot_sync(FULL, bu == wm && bi == wi);
        int ls = __ffs(mk) - 1;
        uint32_t cx = __shfl_sync(FULL, __float_as_uint(bx), ls);
        uint32_t cy = __shfl_sync(FULL, __float_as_uint(by), ls);
        uint32_t cz = __shfl_sync(FULL, __float_as_uint(bz), ls);
        // lanes 0..7: fused store+signal of this warp's candidate to peer=lane
        if (lane < CL) {
            uint32_t slot = (uint32_t)__cvta_generic_to_shared(
                                &s_c[buf][rank * NWARP + w][0]);
            uint32_t mb   = (uint32_t)__cvta_generic_to_shared(&s_mbar[buf]);
            st_async_peer_v4(slot, mb, (uint32_t)lane, wm, wi, cx, cy);
            st_async_peer_b32(slot + 16, mb, (uint32_t)lane, cz);
        }

        // ---- all warps: wait for all 64 contributions, reduce 64 slots ----
        mbar_wait((uint32_t)__cvta_generic_to_shared(&s_mbar[buf]), (uint32_t)((s >> 1) & 1));
        const uint32_t* sc0 = &s_c[buf][lane][0];
        const uint32_t* sc1 = &s_c[buf][lane + 32][0];
        uint32_t v0 = sc0[0], i0 = sc0[1];
        uint32_t v1 = sc1[0], i1 = sc1[1];
        // pairwise: argmax with min-index tie-break
        bool take1 = (v1 > v0) || (v1 == v0 && i1 < i0);
        uint32_t v = take1 ? v1 : v0;
        uint32_t i = take1 ? i1 : i0;
        int myslot = take1 ? (lane + 32) : lane;
        uint32_t gm = __reduce_max_sync(FULL, v);
        uint32_t gi = __reduce_min_sync(FULL, (v == gm) ? i : IDX_INF);
        uint32_t mk2 = __ballot_sync(FULL, v == gm && i == gi);
        int ls2 = __ffs(mk2) - 1;
        int ws = __shfl_sync(FULL, myslot, ls2);
        const uint32_t* wsp = &s_c[buf][ws][0];   // broadcast LDS (same addr all lanes)
        qx = __uint_as_float(wsp[2]);
        qy = __uint_as_float(wsp[3]);
        qz = __uint_as_float(wsp[4]);
    }

    // drain: no CTA exits while peers may still target its smem
    asm volatile("barrier.cluster.arrive.aligned;" ::: "memory");
    asm volatile("barrier.cluster.wait.aligned;" ::: "memory");
}

// ---------------- ball query: one warp per query, first-32-by-index ----------------
__global__ void ball_kernel(const float* __restrict__ xyz,
                            const float* __restrict__ samp) {
    const int warp = (int)((blockIdx.x * blockDim.x + threadIdx.x) >> 5);
    const int lane = threadIdx.x & 31;
    if (warp >= BATCH * N_SAMP) return;
    const int b = warp >> 10;  // 1024 samples per batch
    const float* q = samp + (size_t)warp * 3;
    const float qx = q[0], qy = q[1], qz = q[2];
    const float* __restrict__ X = xyz + (size_t)b * N_PTS * 3;
    int* out = g_nidx + (size_t)warp * K_NEI;

    out[lane] = -1;  // default padding
    int cnt = 0;
    const float R2 = 0.04f;  // f32(0.04): matches JAX weak-typed radius*radius
    for (int base = 0; base < N_PTS && cnt < K_NEI; base += 32) {
        const int i = base + lane;
        float dx = __fsub_rn(qx, X[3 * i + 0]);
        float dy = __fsub_rn(qy, X[3 * i + 1]);
        float dz = __fsub_rn(qz, X[3 * i + 2]);
        float d2 = __fadd_rn(__fadd_rn(__fmul_rn(dx, dx), __fmul_rn(dy, dy)),
                             __fmul_rn(dz, dz));
        const bool in = d2 < R2;
        const unsigned m = __ballot_sync(0xffffffffu, in);
        if (in) {
            int r = cnt + __popc(m & ((1u << lane) - 1u));
            if (r < K_NEI) out[r] = i;
        }
        cnt += __popc(m);
    }
}

// ---------------- gather: one warp per (b,s,k) row, 128 floats ----------------
__global__ void gather_kernel(const float* __restrict__ feat,
                              float* __restrict__ out_feat) {
    const int warp = (int)((blockIdx.x * blockDim.x + threadIdx.x) >> 5);
    const int lane = threadIdx.x & 31;
    if (warp >= BATCH * N_SAMP * K_NEI) return;
    const int b = warp >> 15;  // 1024*32 rows per batch
    int idx = g_nidx[warp];
    int row = (idx < 0) ? N_SAMP : idx;  // -1 -> feat[:, 1024, :]
    const float4* src = (const float4*)(feat + ((size_t)b * N_PTS + row) * C_FEAT);
    float4* dst = (float4*)(out_feat + (size_t)warp * C_FEAT);
    dst[lane] = src[lane];
}

extern "C" void kernel_launch(void* const* d_in, const int* in_sizes, int n_in,
                              void* d_out, int out_size) {
    const float* xyz  = (const float*)d_in[0];
    const float* feat = (const float*)d_in[1];
    if (n_in >= 2 && in_sizes[0] != BATCH * N_PTS * 3) {  // defensive: identify by size
        xyz  = (const float*)d_in[1];
        feat = (const float*)d_in[0];
    }
    float* out = (float*)d_out;
    float* out_feat = out + (size_t)BATCH * N_SAMP * 3;

    fps_kernel<<<BATCH * CL, TPB>>>(xyz, out);

    const int ball_threads = BATCH * N_SAMP * 32;            // one warp/query
    ball_kernel<<<ball_threads / 256, 256>>>(xyz, out);

    const int gath_threads = BATCH * N_SAMP * K_NEI * 32;    // one warp/row
    gather_kernel<<<gath_threads / 256, 256>>>(feat, out_feat);
}

// round 7
// speedup vs baseline: 3.3601x; 1.1948x over previous
#include <cuda_runtime.h>
#include <cstdint>

#define BATCH  4
#define N_PTS  16384
#define N_SAMP 1024
#define K_NEI  32
#define C_FEAT 128
#define CL     8               // cluster size (CTAs per batch)
#define TPB    128
#define NWARP  (TPB / 32)      // 4 warps per CTA
#define PPT    16              // N_PTS / (CL*TPB)
#define NSLOT  (CL * NWARP)    // 32 cluster-wide warp candidates
#define FULL   0xffffffffu
#define IDX_INF 0x7fffffffu
#define TX_BYTES (NSLOT * 24u) // 32 producers x (8B v2 + 16B v4)

// scratch: neighbor indices (device global -> no allocation)
__device__ int g_nidx[BATCH * N_SAMP * K_NEI];

// ---------------- threefry2x32 (JAX-compatible, both output words) ----------------
__device__ __forceinline__ uint32_t rotl32(uint32_t x, int r) {
    return (x << r) | (x >> (32 - r));
}

__device__ __forceinline__ void threefry2x32(uint32_t k0, uint32_t k1,
                                             uint32_t x0, uint32_t x1,
                                             uint32_t& o0, uint32_t& o1) {
    uint32_t ks2 = k0 ^ k1 ^ 0x1BD11BDAu;
    x0 += k0; x1 += k1;
#define TF_RND(r) { x0 += x1; x1 = rotl32(x1, (r)); x1 ^= x0; }
    TF_RND(13) TF_RND(15) TF_RND(26) TF_RND(6)   x0 += k1;  x1 += ks2 + 1u;
    TF_RND(17) TF_RND(29) TF_RND(16) TF_RND(24)  x0 += ks2; x1 += k0 + 2u;
    TF_RND(13) TF_RND(15) TF_RND(26) TF_RND(6)   x0 += k0;  x1 += k1 + 3u;
    TF_RND(17) TF_RND(29) TF_RND(16) TF_RND(24)  x0 += k1;  x1 += ks2 + 4u;
    TF_RND(13) TF_RND(15) TF_RND(26) TF_RND(6)   x0 += ks2; x1 += k0 + 5u;
#undef TF_RND
    o0 = x0; o1 = x1;
}

// start index for batch b (JAX threefry_partitionable=True path):
//   k1,k2 = split(key(42)); bits_b = o0^o1 of tf2x32(k2,(0,b)); start = bits & 16383
__device__ __forceinline__ int jax_start_idx(int b) {
    uint32_t k2a, k2b;
    threefry2x32(0u, 42u, 0u, 1u, k2a, k2b);
    uint32_t o0, o1;
    threefry2x32(k2a, k2b, 0u, (uint32_t)b, o0, o1);
    return (int)((o0 ^ o1) & (uint32_t)(N_PTS - 1));
}

// ---------------- cluster DSMEM / mbarrier helpers ----------------
__device__ __forceinline__ void st_async_peer_v2(uint32_t laddr, uint32_t lmbar,
                                                 uint32_t peer,
                                                 uint32_t a, uint32_t b) {
    uint32_t ra, rm;
    asm volatile("mapa.shared::cluster.u32 %0, %1, %2;" : "=r"(ra) : "r"(laddr), "r"(peer));
    asm volatile("mapa.shared::cluster.u32 %0, %1, %2;" : "=r"(rm) : "r"(lmbar), "r"(peer));
    asm volatile("st.async.shared::cluster.mbarrier::complete_tx::bytes.v2.b32 "
                 "[%0], {%1,%2}, [%3];"
                 :: "r"(ra), "r"(a), "r"(b), "r"(rm) : "memory");
}
__device__ __forceinline__ void st_async_peer_v4(uint32_t laddr, uint32_t lmbar,
                                                 uint32_t peer,
                                                 uint32_t a, uint32_t b,
                                                 uint32_t c, uint32_t d) {
    uint32_t ra, rm;
    asm volatile("mapa.shared::cluster.u32 %0, %1, %2;" : "=r"(ra) : "r"(laddr), "r"(peer));
    asm volatile("mapa.shared::cluster.u32 %0, %1, %2;" : "=r"(rm) : "r"(lmbar), "r"(peer));
    asm volatile("st.async.shared::cluster.mbarrier::complete_tx::bytes.v4.b32 "
                 "[%0], {%1,%2,%3,%4}, [%5];"
                 :: "r"(ra), "r"(a), "r"(b), "r"(c), "r"(d), "r"(rm) : "memory");
}
__device__ __forceinline__ void mbar_expect_tx(uint32_t mbar, uint32_t bytes) {
    asm volatile("mbarrier.arrive.expect_tx.shared.b64 _, [%0], %1;"
                 :: "r"(mbar), "r"(bytes) : "memory");
}
__device__ __forceinline__ void mbar_wait(uint32_t mbar, uint32_t phase) {
    uint32_t done = 0;
    while (!done) {
        asm volatile(
            "{\n\t.reg .pred p;\n\t"
            "mbarrier.try_wait.parity.acquire.cluster.shared::cta.b64 p, [%1], %2, 0x989680;\n\t"
            "selp.b32 %0, 1, 0, p;\n\t}"
            : "=r"(done) : "r"(mbar), "r"(phase) : "memory");
    }
}

// ---------------- FPS: one 8-CTA cluster per batch ----------------
__global__ void __cluster_dims__(CL, 1, 1) fps_kernel(const float* __restrict__ xyz,
                                                      float* __restrict__ out_xyz) {
    const int b = blockIdx.x / CL;
    uint32_t rank;
    asm("mov.u32 %0, %%cluster_ctarank;" : "=r"(rank));
    const float* __restrict__ X = xyz + (size_t)b * N_PTS * 3;
    const int t = threadIdx.x;
    const int base = (int)rank * (TPB * PPT);
    const int w = t >> 5, lane = t & 31;

    // register-resident points + running min distance
    float px[PPT], py[PPT], pz[PPT], md[PPT];
#pragma unroll
    for (int j = 0; j < PPT; j++) {
        int i = base + j * TPB + t;
        px[j] = X[3 * i + 0];
        py[j] = X[3 * i + 1];
        pz[j] = X[3 * i + 2];
        md[j] = __int_as_float(0x7f800000);  // +inf
    }

    // split candidate buffers (double-buffered by step parity):
    //  s_d: {dist,idx} 8B stride -> conflict-free LDS.64 in the reduce
    //  s_p: {x,y,z,pad} 16B stride -> read only as broadcast
    __shared__ uint2 s_d[2][NSLOT];
    __shared__ uint4 s_p[2][NSLOT];
    __shared__ unsigned long long s_mbar[2];

    if (t == 0) {
        asm volatile("mbarrier.init.shared.b64 [%0], %1;"
                     :: "r"((uint32_t)__cvta_generic_to_shared(&s_mbar[0])), "r"(1) : "memory");
        asm volatile("mbarrier.init.shared.b64 [%0], %1;"
                     :: "r"((uint32_t)__cvta_generic_to_shared(&s_mbar[1])), "r"(1) : "memory");
    }
    __syncthreads();
    asm volatile("barrier.cluster.arrive.aligned;" ::: "memory");
    asm volatile("barrier.cluster.wait.aligned;" ::: "memory");

    int cur = jax_start_idx(b);
    float qx = X[3 * cur + 0], qy = X[3 * cur + 1], qz = X[3 * cur + 2];

    for (int s = 0; ; s++) {
        if (rank == 0 && t == 0) {
            float* o = out_xyz + ((size_t)b * N_SAMP + s) * 3;
            o[0] = qx; o[1] = qy; o[2] = qz;
        }
        if (s == N_SAMP - 1) break;

        const int buf = s & 1;
        // arm this phase's mbar (arrival count 1 = this arrive.expect_tx, so the
        // phase cannot flip before this post even if producer bytes land first)
        if (t == 0)
            mbar_expect_tx((uint32_t)__cvta_generic_to_shared(&s_mbar[buf]), TX_BYTES);

        // ---- thread-local update + best (EXACT: no FMA, left-assoc sum) ----
        uint32_t bu = 0u; uint32_t bi = IDX_INF;
        float bx = 0.f, by = 0.f, bz = 0.f;
#pragma unroll
        for (int j = 0; j < PPT; j++) {
            float dx = __fsub_rn(px[j], qx);
            float dy = __fsub_rn(py[j], qy);
            float dz = __fsub_rn(pz[j], qz);
            float d2 = __fadd_rn(__fadd_rn(__fmul_rn(dx, dx), __fmul_rn(dy, dy)),
                                 __fmul_rn(dz, dz));
            float m = fminf(md[j], d2);
            md[j] = m;
            uint32_t mu = __float_as_uint(m);  // m >= 0 -> IEEE order == u32 order
            if (mu > bu) {                     // strict > keeps smaller index (j asc)
                bu = mu; bi = (uint32_t)(base + j * TPB + t);
                bx = px[j]; by = py[j]; bz = pz[j];
            }
        }
        // ---- warp argmax via redux (exact, min-index ties) ----
        uint32_t wm = __reduce_max_sync(FULL, bu);
        uint32_t wi = __reduce_min_sync(FULL, (bu == wm) ? bi : IDX_INF);
        uint32_t mk = __ballot_sync(FULL, bu == wm && bi == wi);
        int ls = __ffs(mk) - 1;
        uint32_t cx = __shfl_sync(FULL, __float_as_uint(bx), ls);
        uint32_t cy = __shfl_sync(FULL, __float_as_uint(by), ls);
        uint32_t cz = __shfl_sync(FULL, __float_as_uint(bz), ls);
        // lanes 0..7: fused store+signal of this warp's candidate to peer=lane
        if (lane < CL) {
            const int slot = (int)rank * NWARP + w;
            uint32_t ad = (uint32_t)__cvta_generic_to_shared(&s_d[buf][slot]);
            uint32_t ap = (uint32_t)__cvta_generic_to_shared(&s_p[buf][slot]);
            uint32_t mb = (uint32_t)__cvta_generic_to_shared(&s_mbar[buf]);
            st_async_peer_v2(ad, mb, (uint32_t)lane, wm, wi);
            st_async_peer_v4(ap, mb, (uint32_t)lane, cx, cy, cz, 0u);
        }

        // ---- all warps: wait for all 32 contributions, reduce (1 slot/lane) ----
        mbar_wait((uint32_t)__cvta_generic_to_shared(&s_mbar[buf]), (uint32_t)((s >> 1) & 1));
        uint2 dv = s_d[buf][lane];
        uint32_t gm = __reduce_max_sync(FULL, dv.x);
        uint32_t gi = __reduce_min_sync(FULL, (dv.x == gm) ? dv.y : IDX_INF);
        uint32_t mk2 = __ballot_sync(FULL, dv.x == gm && dv.y == gi);
        int ws = __ffs(mk2) - 1;                 // winning slot == winning lane
        const uint4 pv = s_p[buf][ws];           // broadcast LDS (same addr all lanes)
        qx = __uint_as_float(pv.x);
        qy = __uint_as_float(pv.y);
        qz = __uint_as_float(pv.z);
    }

    // drain: no CTA exits while peers may still target its smem
    asm volatile("barrier.cluster.arrive.aligned;" ::: "memory");
    asm volatile("barrier.cluster.wait.aligned;" ::: "memory");
}

// ---------------- ball query: one warp per query, first-32-by-index ----------------
__global__ void ball_kernel(const float* __restrict__ xyz,
                            const float* __restrict__ samp) {
    const int warp = (int)((blockIdx.x * blockDim.x + threadIdx.x) >> 5);
    const int lane = threadIdx.x & 31;
    if (warp >= BATCH * N_SAMP) return;
    const int b = warp >> 10;  // 1024 samples per batch
    const float* q = samp + (size_t)warp * 3;
    const float qx = q[0], qy = q[1], qz = q[2];
    const float* __restrict__ X = xyz + (size_t)b * N_PTS * 3;
    int* out = g_nidx + (size_t)warp * K_NEI;

    out[lane] = -1;  // default padding
    int cnt = 0;
    const float R2 = 0.04f;  // f32(0.04): matches JAX weak-typed radius*radius
    for (int base = 0; base < N_PTS && cnt < K_NEI; base += 32) {
        const int i = base + lane;
        float dx = __fsub_rn(qx, X[3 * i + 0]);
        float dy = __fsub_rn(qy, X[3 * i + 1]);
        float dz = __fsub_rn(qz, X[3 * i + 2]);
        float d2 = __fadd_rn(__fadd_rn(__fmul_rn(dx, dx), __fmul_rn(dy, dy)),
                             __fmul_rn(dz, dz));
        const bool in = d2 < R2;
        const unsigned m = __ballot_sync(0xffffffffu, in);
        if (in) {
            int r = cnt + __popc(m & ((1u << lane) - 1u));
            if (r < K_NEI) out[r] = i;
        }
        cnt += __popc(m);
    }
}

// ---------------- gather: one warp per (b,s,k) row, 128 floats ----------------
__global__ void gather_kernel(const float* __restrict__ feat,
                              float* __restrict__ out_feat) {
    const int warp = (int)((blockIdx.x * blockDim.x + threadIdx.x) >> 5);
    const int lane = threadIdx.x & 31;
    if (warp >= BATCH * N_SAMP * K_NEI) return;
    const int b = warp >> 15;  // 1024*32 rows per batch
    int idx = g_nidx[warp];
    int row = (idx < 0) ? N_SAMP : idx;  // -1 -> feat[:, 1024, :]
    const float4* src = (const float4*)(feat + ((size_t)b * N_PTS + row) * C_FEAT);
    float4* dst = (float4*)(out_feat + (size_t)warp * C_FEAT);
    dst[lane] = src[lane];
}

extern "C" void kernel_launch(void* const* d_in, const int* in_sizes, int n_in,
                              void* d_out, int out_size) {
    const float* xyz  = (const float*)d_in[0];
    const float* feat = (const float*)d_in[1];
    if (n_in >= 2 && in_sizes[0] != BATCH * N_PTS * 3) {  // defensive: identify by size
        xyz  = (const float*)d_in[1];
        feat = (const float*)d_in[0];
    }
    float* out = (float*)d_out;
    float* out_feat = out + (size_t)BATCH * N_SAMP * 3;

    fps_kernel<<<BATCH * CL, TPB>>>(xyz, out);

    const int ball_threads = BATCH * N_SAMP * 32;            // one warp/query
    ball_kernel<<<ball_threads / 256, 256>>>(xyz, out);

    const int gath_threads = BATCH * N_SAMP * K_NEI * 32;    // one warp/row
    gather_kernel<<<gath_threads / 256, 256>>>(feat, out_feat);
}